// round 14
// baseline (speedup 1.0000x reference)
#include <cuda_runtime.h>
#include <cuda_fp16.h>

#define N_ANGLES  180
#define N_DET     256
#define IMG       256
#define G_ANGLES  2
#define N_GROUPS  (N_ANGLES / G_ANGLES)   // 90
#define N_SLABS   8
#define SLAB_H    32
#define THREADS   256
#define P2        257                     // half2-pairs per row (256 + 1 pad); 257 mod 32 = 1 -> conflict-free
#define LROWS     35                      // slab rows 32 + guard rows (-1, +32, +33)
#define ROWB      (P2 * 4)                // row stride in bytes
#define SMEM_BYTES (LROWS * ROWB)         // 35980 B
#define OUT_ELEMS (8 * N_ANGLES * N_DET)

__device__ float g_scratch[N_SLABS][OUT_ELEMS];   // slab partials (11.8 MB)

// Clamp before float->int: raw cvt saturates and later +/-1 wraps (R7 crash).
__device__ __forceinline__ int ifloor_c(float v) {
    return (int)floorf(fminf(fmaxf(v, -1.0e6f), 1.0e6f));
}
__device__ __forceinline__ int iceil_c(float v) {
    return (int)ceilf(fminf(fmaxf(v, -1.0e6f), 1.0e6f));
}

__device__ __forceinline__ void slab_clip(float p0, float d, float lo, float hi,
                                          float& t0, float& t1) {
    if (fabsf(d) > 1e-12f) {
        float inv = 1.0f / d;
        float a = (lo - p0) * inv;
        float b = (hi - p0) * inv;
        t0 = fmaxf(t0, fminf(a, b));
        t1 = fminf(t1, fmaxf(a, b));
    } else if (p0 < lo || p0 > hi) {
        t0 = 1.0e6f; t1 = -1.0e6f;
    }
}

// Edge-band sample reading texels (low half of each pair, 4B stride).
// Rows always in-slab via guard rows; only x needs guarding.
__device__ __forceinline__ float edge_sample(const char* __restrict__ sb, int row_lo,
                                             float X0, float Y0, float dx, float dy, int k) {
    float x = fmaf((float)k, dx, X0);
    float y = fmaf((float)k, dy, Y0);
    int xi = __float2int_rd(x);
    int yi = __float2int_rd(y);
    float wx = x - (float)xi;
    float wy = y - (float)yi;
    const char* rp = sb + (yi - row_lo) * ROWB;
    int x0c = min(255, max(0, xi));
    int x1c = min(255, max(0, xi + 1));
    bool g0 = ((unsigned)xi < 256u);
    bool g1 = ((unsigned)(xi + 1) < 256u);
    float v00 = g0 ? __half2float(*(const __half*)(rp + x0c * 4)) : 0.0f;
    float v01 = g1 ? __half2float(*(const __half*)(rp + x1c * 4)) : 0.0f;
    float v10 = g0 ? __half2float(*(const __half*)(rp + ROWB + x0c * 4)) : 0.0f;
    float v11 = g1 ? __half2float(*(const __half*)(rp + ROWB + x1c * 4)) : 0.0f;
    float r0 = fmaf(wx, v01 - v00, v00);
    float r1 = fmaf(wx, v11 - v10, v10);
    return fmaf(wy, r1 - r0, r0);
}

__global__ __launch_bounds__(THREADS, 4)
void radon_slab_kernel(const float* __restrict__ in) {
    extern __shared__ char smem[];

    int b     = blockIdx.x;
    int slab  = b & 7;
    int rem   = b >> 3;
    int grp   = rem % N_GROUPS;
    int batch = rem / N_GROUPS;
    int row_lo = slab * SLAB_H - 1;

    // Axis flip keeps |dy_eff| >= 0.707 for every angle (slab axis = fast axis).
    bool flipped = (grp >= 23 && grp <= 67);   // angles 46..135

    // ---- Stage slab as half2 PAIRS: pair[x] = (v[x], v[x+1]); OOB = 0 ----
    const float* img = in + (size_t)batch * IMG * IMG;
    if (!flipped) {
        for (int j = threadIdx.x; j < LROWS * 64; j += THREADS) {
            int L  = j >> 6;
            int c4 = (j & 63) << 2;
            int g  = row_lo + L;
            float4 v = make_float4(0.f, 0.f, 0.f, 0.f);
            float v4 = 0.f;
            if ((unsigned)g < 256u) {
                v = *(const float4*)(img + g * 256 + c4);
                if (c4 + 4 < 256) v4 = img[g * 256 + c4 + 4];
            }
            __half2* prow = (__half2*)smem + L * P2 + c4;
            prow[0] = __floats2half2_rn(v.x, v.y);
            prow[1] = __floats2half2_rn(v.y, v.z);
            prow[2] = __floats2half2_rn(v.z, v.w);
            prow[3] = __floats2half2_rn(v.w, v4);
        }
    } else {
        // transposed: eff-row L = original column (row_lo+L); pair needs next column too
        for (int i = threadIdx.x; i < LROWS * 256; i += THREADS) {
            int L = i >> 8;                 // eff row (original x)
            int y = i & 255;                // eff col (original y)
            int g = row_lo + L;
            float a = 0.f, c = 0.f;
            if ((unsigned)g < 256u) {
                a = img[y * 256 + g];
                if (y + 1 < 256) c = img[(y + 1) * 256 + g];
            }
            ((__half2*)smem)[L * P2 + y] = __floats2half2_rn(a, c);
        }
    }
    __syncthreads();

    const char* sb = smem;     // pair array base (row index = yi - row_lo)

    for (int r = threadIdx.x; r < G_ANGLES * N_DET; r += THREADS) {
        int aL = r >> 8;
        int d  = r & 255;
        int a  = grp * G_ANGLES + aL;

        float theta = (float)a * 0.017453292519943295f;
        float sn, cs;
        sincosf(theta, &sn, &cs);
        float sd = (float)d - 127.5f;
        float X0n = fmaf(sd, cs, fmaf(127.5f, sn, 127.5f));
        float Y0n = fmaf(sd, sn, fmaf(-127.5f, cs, 127.5f));
        float X0 = flipped ? Y0n : X0n;
        float Y0 = flipped ? X0n : Y0n;
        float dx = flipped ? cs  : -sn;
        float dy = flipped ? -sn : cs;      // |dy| >= 0.707 always

        // Outer nonzero-contribution range (margins keep yi in [-1,255])
        float t0 = 0.0f, t1 = 255.0f;
        slab_clip(X0, dx, -0.999f, 255.999f, t0, t1);
        slab_clip(Y0, dy, -0.999f, 255.999f, t0, t1);
        int k0 = max(0,   iceil_c(t0));
        int k1 = min(255, ifloor_c(t1));

        // Exact y-slab partition: adjacent slabs evaluate the SAME clamped float
        // expressions -> each k claimed exactly once; guard rows absorb ulp drift.
        {
            float inv = 1.0f / dy;
            if (dy > 0.0f) {
                if (slab > 0) k0 = max(k0, iceil_c(((float)(slab * SLAB_H) - Y0) * inv));
                if (slab < N_SLABS - 1) k1 = min(k1, iceil_c(((float)((slab + 1) * SLAB_H) - Y0) * inv) - 1);
            } else {
                if (slab < N_SLABS - 1) k0 = max(k0, ifloor_c(((float)((slab + 1) * SLAB_H) - Y0) * inv) + 1);
                if (slab > 0) k1 = min(k1, ifloor_c(((float)(slab * SLAB_H) - Y0) * inv));
            }
        }

        // x-interior: all taps valid in x -> guard-free fast loop
        float ti0 = 0.0f, ti1 = 255.0f;
        slab_clip(X0, dx, 0.002f, 254.998f, ti0, ti1);
        int ki0 = max(k0, iceil_c(ti0));
        int ki1 = min(k1, ifloor_c(ti1));
        if (ki0 > ki1) { ki0 = k1 + 1; ki1 = k1; }

        float acc = 0.0f;

        int e1 = min(ki0 - 1, k1);
        for (int k = k0; k <= e1; ++k)
            acc += edge_sample(sb, row_lo, X0, Y0, dx, dy, k);

        // ---- Interior fast loop: magic-floor (no F2I/I2F), paired half2 loads ----
        // +2 coordinate bias keeps magic-floor valid (arg >= 0.5) even at y ~ -1.
        const float MAGIC  = 8388607.5f;   // 2^23 - 0.5
        const float MAGIC2 = 8388608.0f;   // 2^23
        float X0b = X0 + 2.0f;
        float Y0b = Y0 + 2.0f;
        // byte offset = yi_raw*ROWB + xi_raw*4 + baseC, yi_raw = floor(y)+2 (mod ties->even, wy/wx in {0,1} compensate)
        int baseC = -(((2 + row_lo) * P2 + 2) << 2);

        float kf = (float)ki0;
        #pragma unroll 4
        for (int k = ki0; k <= ki1; ++k) {
            float x = fmaf(kf, dx, X0b);
            float y = fmaf(kf, dy, Y0b);
            kf += 1.0f;
            float tx = x + MAGIC;
            float ty = y + MAGIC;
            float wx = x - (tx - MAGIC2);
            float wy = y - (ty - MAGIC2);
            int xi = __float_as_int(tx) & 0xFFFF;
            int yi = __float_as_int(ty) & 0xFFFF;
            int off = yi * ROWB + (xi << 2) + baseC;
            __half2 p0 = *(const __half2*)(sb + off);
            __half2 p1 = *(const __half2*)(sb + off + ROWB);
            __half2 dv = __hsub2(p1, p0);
            __half2 m  = __hfma2(__float2half2_rn(wy), dv, p0);
            float f0 = __low2float(m);
            float f1 = __high2float(m);
            acc = fmaf(wx, f1 - f0, acc + f0);
        }

        int e2 = max(ki1 + 1, k0);
        for (int k = e2; k <= k1; ++k)
            acc += edge_sample(sb, row_lo, X0, Y0, dx, dy, k);

        g_scratch[slab][((size_t)batch * N_ANGLES + a) * N_DET + d] = acc;
    }
}

__global__ void radon_reduce_kernel(float* __restrict__ out) {
    int i = blockIdx.x * blockDim.x + threadIdx.x;   // float4 index
    if (i < OUT_ELEMS / 4) {
        float4 r = make_float4(0.f, 0.f, 0.f, 0.f);
        #pragma unroll
        for (int s = 0; s < N_SLABS; ++s) {
            float4 v = ((const float4*)g_scratch[s])[i];
            r.x += v.x; r.y += v.y; r.z += v.z; r.w += v.w;
        }
        ((float4*)out)[i] = r;
    }
}

extern "C" void kernel_launch(void* const* d_in, const int* in_sizes, int n_in,
                              void* d_out, int out_size) {
    (void)in_sizes; (void)n_in; (void)out_size;
    radon_slab_kernel<<<8 * N_GROUPS * N_SLABS, THREADS, SMEM_BYTES>>>((const float*)d_in[0]);
    radon_reduce_kernel<<<(OUT_ELEMS / 4 + 255) / 256, 256>>>((float*)d_out);
}

// round 17
// speedup vs baseline: 1.8324x; 1.8324x over previous
#include <cuda_runtime.h>
#include <cuda_fp16.h>

#define N_ANGLES  180
#define N_DET     256
#define IMG       256
#define G_ANGLES  2
#define N_GROUPS  (N_ANGLES / G_ANGLES)   // 90
#define N_SLABS   4
#define SLAB_H    64
#define THREADS   256
#define P2        257                     // half2-pairs per row; 257 mod 32 = 1 -> conflict-free
#define LROWS     67                      // slab rows 64 + guard rows (-1, +64, +65)
#define ROWB      (P2 * 4)                // row stride in bytes (1028)
#define SMEM_BYTES (LROWS * ROWB)         // 68876 B -> 3 blocks/SM (needs FuncSetAttribute!)
#define OUT_ELEMS (8 * N_ANGLES * N_DET)

__device__ float g_scratch[N_SLABS][OUT_ELEMS];   // slab partials (5.9 MB)

// Clamp before float->int: raw cvt saturates and later +/-1 wraps (R7 crash).
__device__ __forceinline__ int ifloor_c(float v) {
    return (int)floorf(fminf(fmaxf(v, -1.0e6f), 1.0e6f));
}
__device__ __forceinline__ int iceil_c(float v) {
    return (int)ceilf(fminf(fmaxf(v, -1.0e6f), 1.0e6f));
}

__device__ __forceinline__ void slab_clip(float p0, float d, float lo, float hi,
                                          float& t0, float& t1) {
    if (fabsf(d) > 1e-12f) {
        float inv = 1.0f / d;
        float a = (lo - p0) * inv;
        float b = (hi - p0) * inv;
        t0 = fmaxf(t0, fminf(a, b));
        t1 = fminf(t1, fmaxf(a, b));
    } else if (p0 < lo || p0 > hi) {
        t0 = 1.0e6f; t1 = -1.0e6f;
    }
}

// Edge-band sample reading texels (low half of each pair, 4B stride).
// Rows always in-slab via guard rows; only x needs guarding.
__device__ __forceinline__ float edge_sample(const char* __restrict__ sb, int row_lo,
                                             float X0, float Y0, float dx, float dy, int k) {
    float x = fmaf((float)k, dx, X0);
    float y = fmaf((float)k, dy, Y0);
    int xi = __float2int_rd(x);
    int yi = __float2int_rd(y);
    float wx = x - (float)xi;
    float wy = y - (float)yi;
    const char* rp = sb + (yi - row_lo) * ROWB;
    int x0c = min(255, max(0, xi));
    int x1c = min(255, max(0, xi + 1));
    bool g0 = ((unsigned)xi < 256u);
    bool g1 = ((unsigned)(xi + 1) < 256u);
    float v00 = g0 ? __half2float(*(const __half*)(rp + x0c * 4)) : 0.0f;
    float v01 = g1 ? __half2float(*(const __half*)(rp + x1c * 4)) : 0.0f;
    float v10 = g0 ? __half2float(*(const __half*)(rp + ROWB + x0c * 4)) : 0.0f;
    float v11 = g1 ? __half2float(*(const __half*)(rp + ROWB + x1c * 4)) : 0.0f;
    float r0 = fmaf(wx, v01 - v00, v00);
    float r1 = fmaf(wx, v11 - v10, v10);
    return fmaf(wy, r1 - r0, r0);
}

__global__ __launch_bounds__(THREADS, 3)
void radon_slab_kernel(const float* __restrict__ in) {
    extern __shared__ char smem[];

    int b     = blockIdx.x;
    int slab  = b & 3;
    int rem   = b >> 2;
    int grp   = rem % N_GROUPS;
    int batch = rem / N_GROUPS;
    int row_lo = slab * SLAB_H - 1;

    // Axis flip keeps |dy_eff| >= 0.69 for every angle (slab axis = fast axis).
    bool flipped = (grp >= 23 && grp <= 67);   // angles 46..135

    // ---- Stage slab as half2 PAIRS: pair[x] = (v[x], v[x+1]); OOB = 0 ----
    const float* img = in + (size_t)batch * IMG * IMG;
    if (!flipped) {
        for (int j = threadIdx.x; j < LROWS * 64; j += THREADS) {
            int L  = j >> 6;
            int c4 = (j & 63) << 2;
            int g  = row_lo + L;
            float4 v = make_float4(0.f, 0.f, 0.f, 0.f);
            float v4 = 0.f;
            if ((unsigned)g < 256u) {
                v = *(const float4*)(img + g * 256 + c4);
                if (c4 + 4 < 256) v4 = img[g * 256 + c4 + 4];
            }
            __half2* prow = (__half2*)smem + L * P2 + c4;
            prow[0] = __floats2half2_rn(v.x, v.y);
            prow[1] = __floats2half2_rn(v.y, v.z);
            prow[2] = __floats2half2_rn(v.z, v.w);
            prow[3] = __floats2half2_rn(v.w, v4);
        }
    } else {
        // Transposed staging, COALESCED: j (original x, consecutive) innermost so
        // warp lanes read consecutive floats of one image row. (R14 had y innermost
        // -> 32 sectors/warp-LDG -> L1-queue meltdown, +146us.)
        for (int i = threadIdx.x; i < 256 * LROWS; i += THREADS) {
            int y = i / LROWS;              // eff col (original y)
            int j = i - y * LROWS;          // eff row (original x), consecutive per lane
            int g = row_lo + j;
            float a = 0.f, c = 0.f;
            if ((unsigned)g < 256u) {
                a = img[y * 256 + g];
                if (y + 1 < 256) c = img[(y + 1) * 256 + g];
            }
            // word index j*257+y: consecutive j -> distinct banks (257 mod 32 = 1)
            ((__half2*)smem)[j * P2 + y] = __floats2half2_rn(a, c);
        }
    }
    __syncthreads();

    const char* sb = smem;

    for (int r = threadIdx.x; r < G_ANGLES * N_DET; r += THREADS) {
        int aL = r >> 8;
        int d  = r & 255;
        int a  = grp * G_ANGLES + aL;

        float theta = (float)a * 0.017453292519943295f;
        float sn, cs;
        sincosf(theta, &sn, &cs);
        float sd = (float)d - 127.5f;
        float X0n = fmaf(sd, cs, fmaf(127.5f, sn, 127.5f));
        float Y0n = fmaf(sd, sn, fmaf(-127.5f, cs, 127.5f));
        float X0 = flipped ? Y0n : X0n;
        float Y0 = flipped ? X0n : Y0n;
        float dx = flipped ? cs  : -sn;
        float dy = flipped ? -sn : cs;      // |dy| >= 0.69 always

        // Outer nonzero-contribution range (margins keep yi in [-1,255])
        float t0 = 0.0f, t1 = 255.0f;
        slab_clip(X0, dx, -0.999f, 255.999f, t0, t1);
        slab_clip(Y0, dy, -0.999f, 255.999f, t0, t1);
        int k0 = max(0,   iceil_c(t0));
        int k1 = min(255, ifloor_c(t1));

        // Exact y-slab partition: adjacent slabs evaluate the SAME clamped float
        // expressions -> each k claimed exactly once; guard rows absorb ulp drift.
        {
            float inv = 1.0f / dy;
            if (dy > 0.0f) {
                if (slab > 0) k0 = max(k0, iceil_c(((float)(slab * SLAB_H) - Y0) * inv));
                if (slab < N_SLABS - 1) k1 = min(k1, iceil_c(((float)((slab + 1) * SLAB_H) - Y0) * inv) - 1);
            } else {
                if (slab < N_SLABS - 1) k0 = max(k0, ifloor_c(((float)((slab + 1) * SLAB_H) - Y0) * inv) + 1);
                if (slab > 0) k1 = min(k1, ifloor_c(((float)(slab * SLAB_H) - Y0) * inv));
            }
        }

        // x-interior: all taps valid in x -> guard-free fast loop
        float ti0 = 0.0f, ti1 = 255.0f;
        slab_clip(X0, dx, 0.002f, 254.998f, ti0, ti1);
        int ki0 = max(k0, iceil_c(ti0));
        int ki1 = min(k1, ifloor_c(ti1));
        if (ki0 > ki1) { ki0 = k1 + 1; ki1 = k1; }

        float acc = 0.0f;

        int e1 = min(ki0 - 1, k1);
        for (int k = k0; k <= e1; ++k)
            acc += edge_sample(sb, row_lo, X0, Y0, dx, dy, k);

        // ---- Interior fast loop: magic-floor (no F2I/I2F), paired half2 loads ----
        // +2 bias keeps the magic argument >= 0.5 even at y ~ -1; ties round to
        // even -> w in {0,1}, both bilinear-exact.
        const float MAGIC  = 8388607.5f;   // 2^23 - 0.5
        const float MAGIC2 = 8388608.0f;   // 2^23
        float X0b = X0 + 2.0f;
        float Y0b = Y0 + 2.0f;
        int baseC = -(((2 + row_lo) * P2 + 2) << 2);

        float kf = (float)ki0;
        #pragma unroll 4
        for (int k = ki0; k <= ki1; ++k) {
            float x = fmaf(kf, dx, X0b);
            float y = fmaf(kf, dy, Y0b);
            kf += 1.0f;
            float tx = x + MAGIC;
            float ty = y + MAGIC;
            float wx = x - (tx - MAGIC2);
            float wy = y - (ty - MAGIC2);
            int xi = __float_as_int(tx) & 0xFFFF;
            int yi = __float_as_int(ty) & 0xFFFF;
            int off = yi * ROWB + (xi << 2) + baseC;
            __half2 p0 = *(const __half2*)(sb + off);
            __half2 p1 = *(const __half2*)(sb + off + ROWB);
            __half2 dv = __hsub2(p1, p0);
            __half2 m  = __hfma2(__float2half2_rn(wy), dv, p0);
            float f0 = __low2float(m);
            float f1 = __high2float(m);
            acc = fmaf(wx, f1 - f0, acc + f0);
        }

        int e2 = max(ki1 + 1, k0);
        for (int k = e2; k <= k1; ++k)
            acc += edge_sample(sb, row_lo, X0, Y0, dx, dy, k);

        g_scratch[slab][((size_t)batch * N_ANGLES + a) * N_DET + d] = acc;
    }
}

__global__ void radon_reduce_kernel(float* __restrict__ out) {
    int i = blockIdx.x * blockDim.x + threadIdx.x;   // float4 index
    if (i < OUT_ELEMS / 4) {
        float4 a = ((const float4*)g_scratch[0])[i];
        float4 b = ((const float4*)g_scratch[1])[i];
        float4 c = ((const float4*)g_scratch[2])[i];
        float4 d = ((const float4*)g_scratch[3])[i];
        float4 r;
        r.x = (a.x + b.x) + (c.x + d.x);
        r.y = (a.y + b.y) + (c.y + d.y);
        r.z = (a.z + b.z) + (c.z + d.z);
        r.w = (a.w + b.w) + (c.w + d.w);
        ((float4*)out)[i] = r;
    }
}

extern "C" void kernel_launch(void* const* d_in, const int* in_sizes, int n_in,
                              void* d_out, int out_size) {
    (void)in_sizes; (void)n_in; (void)out_size;
    // 68876 B > 48KB default dynamic-smem cap: the attribute is REQUIRED
    // (dropping it was the sole cause of the R16 capture failure).
    static bool attr_set = false;
    if (!attr_set) {
        cudaFuncSetAttribute(radon_slab_kernel,
                             cudaFuncAttributeMaxDynamicSharedMemorySize, SMEM_BYTES);
        attr_set = true;
    }
    radon_slab_kernel<<<8 * N_GROUPS * N_SLABS, THREADS, SMEM_BYTES>>>((const float*)d_in[0]);
    radon_reduce_kernel<<<(OUT_ELEMS / 4 + 255) / 256, 256>>>((float*)d_out);
}